// round 6
// baseline (speedup 1.0000x reference)
#include <cuda_runtime.h>
#include <cuda_bf16.h>
#include <cstdint>
#include <cstddef>

#define Bq   2
#define Sq   2048
#define HIDD 2048
#define NH   32
#define NKV  8
#define HD   64
#define QKVW ((NH + 2 * NKV) * HD)   /* 3072 */
#define GROUP (NH / NKV)             /* 4 */
#define SCALE 0.125f
#define LOG2E 1.4426950408889634f
#define QSCALE (SCALE * LOG2E)

#define MROWS   (Bq * Sq)            /* 4096 */
#define N_HID   (NH * HD)            /* 2048 */

// ---------------------------------------------------------------------------
// Scratch (device globals)
// ---------------------------------------------------------------------------
__device__ float g_qkv [(size_t)Bq * Sq * QKVW];

__device__ __nv_bfloat16 g_hid_hi [(size_t)MROWS * HIDD];
__device__ __nv_bfloat16 g_hid_lo [(size_t)MROWS * HIDD];
__device__ __nv_bfloat16 g_wqkvT_hi[(size_t)QKVW * HIDD];
__device__ __nv_bfloat16 g_wqkvT_lo[(size_t)QKVW * HIDD];
__device__ __nv_bfloat16 g_woT_hi [(size_t)HIDD * N_HID];
__device__ __nv_bfloat16 g_woT_lo [(size_t)HIDD * N_HID];
__device__ __nv_bfloat16 g_attn_hi[(size_t)MROWS * N_HID];
__device__ __nv_bfloat16 g_attn_lo[(size_t)MROWS * N_HID];

// K bf16 hi/lo: [b, hk, kv, d]; V^T bf16 hi/lo: [b, hk, d, kv]
__device__ __nv_bfloat16 g_k_hi [(size_t)Bq * NKV * Sq * HD];
__device__ __nv_bfloat16 g_k_lo [(size_t)Bq * NKV * Sq * HD];
__device__ __nv_bfloat16 g_vt_hi[(size_t)Bq * NKV * HD * Sq];
__device__ __nv_bfloat16 g_vt_lo[(size_t)Bq * NKV * HD * Sq];

// ---------------------------------------------------------------------------
// Helpers
// ---------------------------------------------------------------------------
__device__ __forceinline__ uint32_t smem_u32(const void* p) {
    uint32_t a;
    asm("{ .reg .u64 t; cvta.to.shared.u64 t, %1; cvt.u32.u64 %0, t; }"
        : "=r"(a) : "l"(p));
    return a;
}
__device__ __forceinline__ uint32_t packbf(float x, float y) {   // lo=x, hi=y
    uint32_t r;
    asm("cvt.rn.bf16x2.f32 %0, %1, %2;" : "=r"(r) : "f"(y), "f"(x));
    return r;
}
__device__ __forceinline__ float2 unpackbf(uint32_t v) {
    __nv_bfloat162 t = *reinterpret_cast<__nv_bfloat162*>(&v);
    return make_float2(__bfloat162float(t.x), __bfloat162float(t.y));
}
__device__ __forceinline__ float ex2(float x) {
    float r; asm("ex2.approx.f32 %0, %1;" : "=f"(r) : "f"(x)); return r;
}

#define MMA_BF16(c, a, br0, br1) \
    asm volatile("mma.sync.aligned.m16n8k16.row.col.f32.bf16.bf16.f32 " \
        "{%0,%1,%2,%3}, {%4,%5,%6,%7}, {%8,%9}, {%0,%1,%2,%3};" \
        : "+f"((c)[0]), "+f"((c)[1]), "+f"((c)[2]), "+f"((c)[3]) \
        : "r"((a)[0]), "r"((a)[1]), "r"((a)[2]), "r"((a)[3]), "r"(br0), "r"(br1))

#define LDMATRIX_X4(r, addr) \
    asm volatile("ldmatrix.sync.aligned.m8n8.x4.shared.b16 {%0,%1,%2,%3}, [%4];" \
        : "=r"((r)[0]), "=r"((r)[1]), "=r"((r)[2]), "=r"((r)[3]) : "r"(addr))

#define CP_ASYNC16(saddr, gptr) \
    asm volatile("cp.async.cg.shared.global [%0], [%1], 16;" :: "r"(saddr), "l"(gptr))
#define CP_COMMIT() asm volatile("cp.async.commit_group;" ::: "memory")
template <int N> __device__ __forceinline__ void cp_wait() {
    asm volatile("cp.async.wait_group %0;" :: "n"(N) : "memory");
}

// ---------------------------------------------------------------------------
// fp32 -> bf16 hi/lo split
// ---------------------------------------------------------------------------
__global__ void convert_split(const float* __restrict__ x,
                              __nv_bfloat16* __restrict__ hi,
                              __nv_bfloat16* __restrict__ lo, int n4)
{
    int i = blockIdx.x * blockDim.x + threadIdx.x;
    if (i >= n4) return;
    float4 v = ((const float4*)x)[i];
    uint32_t h01 = packbf(v.x, v.y), h23 = packbf(v.z, v.w);
    float2 f01 = unpackbf(h01), f23 = unpackbf(h23);
    uint32_t l01 = packbf(v.x - f01.x, v.y - f01.y);
    uint32_t l23 = packbf(v.z - f23.x, v.w - f23.y);
    ((uint2*)hi)[i] = make_uint2(h01, h23);
    ((uint2*)lo)[i] = make_uint2(l01, l23);
}

// ---------------------------------------------------------------------------
// Transpose fp32 B[R x C] -> bf16 hi/lo [C x R]
// ---------------------------------------------------------------------------
__global__ void transpose_split(const float* __restrict__ B,
                                __nv_bfloat16* __restrict__ Thi,
                                __nv_bfloat16* __restrict__ Tlo, int R, int C)
{
    __shared__ float t[32][33];
    int x = blockIdx.x * 32 + threadIdx.x;
    int y = blockIdx.y * 32 + threadIdx.y;
    #pragma unroll
    for (int j = 0; j < 32; j += 8)
        t[threadIdx.y + j][threadIdx.x] = B[(size_t)(y + j) * C + x];
    __syncthreads();
    int ox = blockIdx.y * 32 + threadIdx.x;
    int oy = blockIdx.x * 32 + threadIdx.y;
    #pragma unroll
    for (int j = 0; j < 32; j += 8) {
        float v = t[threadIdx.x][threadIdx.y + j];
        __nv_bfloat16 h = __float2bfloat16(v);
        Thi[(size_t)(oy + j) * R + ox] = h;
        Tlo[(size_t)(oy + j) * R + ox] = __float2bfloat16(v - __bfloat162float(h));
    }
}

// ---------------------------------------------------------------------------
// GEMM: C[M,N] = A[M,K] * B^T, 3-product bf16.
// CTA tile 256x128, 8 warps (warp tile 64x64), K-chunk 32, 2-stage pipeline,
// one __syncthreads per chunk.
// ---------------------------------------------------------------------------
#define ROWB     80
#define G_AHI    0
#define G_ALO    (256 * ROWB)             /* 20480 */
#define G_BHI    (2 * 256 * ROWB)         /* 40960 */
#define G_BLO    (G_BHI + 128 * ROWB)     /* 51200 */
#define G_STAGE  (G_BHI + 2 * 128 * ROWB) /* 61440 */
#define GEMM_SMEM (2 * G_STAGE)           /* 122880 */

__global__ __launch_bounds__(256, 1) void gemm_mma(
    int M, int N, int K,
    const __nv_bfloat16* __restrict__ Ahi, const __nv_bfloat16* __restrict__ Alo,
    const __nv_bfloat16* __restrict__ Bhi, const __nv_bfloat16* __restrict__ Blo,
    float* __restrict__ C)
{
    extern __shared__ char smem[];
    const uint32_t sbase = smem_u32(smem);
    const int tid  = threadIdx.x;
    const int wid  = tid >> 5;
    const int lane = tid & 31;
    const int m0 = blockIdx.y * 256;
    const int n0 = blockIdx.x * 128;
    const int wm = (wid >> 1) * 64;      // 0,64,128,192
    const int wn = (wid & 1) * 64;       // 0,64

    const __nv_bfloat16* Ahi_p = Ahi + (size_t)m0 * K;
    const __nv_bfloat16* Alo_p = Alo + (size_t)m0 * K;
    const __nv_bfloat16* Bhi_p = Bhi + (size_t)n0 * K;
    const __nv_bfloat16* Blo_p = Blo + (size_t)n0 * K;

    const int q  = lane >> 3;
    const int ri = lane & 7;
    const int a_row_add = ((q & 1) << 3) + ri;
    const int a_col_add = (q >> 1) << 3;
    const int b_row_add = ((q >> 1) << 3) + ri;
    const int b_col_add = (q & 1) << 3;

    float acc[4][8][4];
    #pragma unroll
    for (int mi = 0; mi < 4; mi++)
        #pragma unroll
        for (int ni = 0; ni < 8; ni++)
            #pragma unroll
            for (int c = 0; c < 4; c++) acc[mi][ni][c] = 0.f;

    const int NC = K >> 5;

    auto load_chunk = [&](int stage, int k0) {
        uint32_t sdst = sbase + stage * G_STAGE;
        #pragma unroll
        for (int u = 0; u < 4; u++) {
            int idx = tid + u * 256;        // 0..1023
            int row = idx >> 2, seg = idx & 3;
            size_t go = (size_t)row * K + k0 + seg * 8;
            uint32_t so = row * ROWB + seg * 16;
            CP_ASYNC16(sdst + G_AHI + so, Ahi_p + go);
            CP_ASYNC16(sdst + G_ALO + so, Alo_p + go);
        }
        #pragma unroll
        for (int u = 0; u < 2; u++) {
            int idx = tid + u * 256;        // 0..511
            int row = idx >> 2, seg = idx & 3;
            size_t go = (size_t)row * K + k0 + seg * 8;
            uint32_t so = row * ROWB + seg * 16;
            CP_ASYNC16(sdst + G_BHI + so, Bhi_p + go);
            CP_ASYNC16(sdst + G_BLO + so, Blo_p + go);
        }
        CP_COMMIT();
    };

    load_chunk(0, 0);

    for (int i = 0; i < NC; i++) {
        const int s = i & 1;
        cp_wait<0>();
        __syncthreads();
        if (i + 1 < NC) load_chunk(s ^ 1, (i + 1) << 5);

        const uint32_t st = sbase + s * G_STAGE;
        #pragma unroll
        for (int kk = 0; kk < 32; kk += 16) {
            uint32_t a_hi[4][4], a_lo[4][4];
            #pragma unroll
            for (int mi = 0; mi < 4; mi++) {
                int row = wm + mi * 16 + a_row_add;
                int col = kk + a_col_add;
                LDMATRIX_X4(a_hi[mi], st + G_AHI + row * ROWB + col * 2);
                LDMATRIX_X4(a_lo[mi], st + G_ALO + row * ROWB + col * 2);
            }
            #pragma unroll
            for (int nj = 0; nj < 4; nj++) {
                uint32_t bh[4], bl[4];
                int row = wn + nj * 16 + b_row_add;
                int col = kk + b_col_add;
                LDMATRIX_X4(bh, st + G_BHI + row * ROWB + col * 2);
                LDMATRIX_X4(bl, st + G_BLO + row * ROWB + col * 2);
                #pragma unroll
                for (int mi = 0; mi < 4; mi++) {
                    #pragma unroll
                    for (int hh = 0; hh < 2; hh++) {
                        int ni = nj * 2 + hh;
                        MMA_BF16(acc[mi][ni], a_hi[mi], bh[hh*2], bh[hh*2+1]);
                        MMA_BF16(acc[mi][ni], a_hi[mi], bl[hh*2], bl[hh*2+1]);
                        MMA_BF16(acc[mi][ni], a_lo[mi], bh[hh*2], bh[hh*2+1]);
                    }
                }
            }
        }
    }

    const int g  = lane >> 2;
    const int tg = lane & 3;
    #pragma unroll
    for (int mi = 0; mi < 4; mi++) {
        #pragma unroll
        for (int ni = 0; ni < 8; ni++) {
            int row = m0 + wm + mi * 16 + g;
            int col = n0 + wn + ni * 8 + tg * 2;
            *(float2*)(C + (size_t)row * N + col)       = make_float2(acc[mi][ni][0], acc[mi][ni][1]);
            *(float2*)(C + (size_t)(row + 8) * N + col) = make_float2(acc[mi][ni][2], acc[mi][ni][3]);
        }
    }
}

// ---------------------------------------------------------------------------
// RoPE
// ---------------------------------------------------------------------------
__global__ void rope_kernel(const int* __restrict__ positions)
{
    const int total = Bq * Sq * (NH + NKV) * (HD / 2);
    int idx = blockIdx.x * blockDim.x + threadIdx.x;
    if (idx >= total) return;

    int i  = idx & (HD / 2 - 1);
    int hh = (idx >> 5) % (NH + NKV);
    int bs = idx / ((HD / 2) * (NH + NKV));

    float pos = (float)positions[bs];
    float inv = __expf(-((float)(2 * i) / (float)HD) * 9.210340371976184f);
    float f = pos * inv;
    float c = cosf(f), s = sinf(f);

    float* p = g_qkv + (size_t)bs * QKVW + hh * HD;
    float x1 = p[i];
    float x2 = p[i + HD / 2];
    p[i]          = x1 * c - x2 * s;
    p[i + HD / 2] = x2 * c + x1 * s;
}

// ---------------------------------------------------------------------------
// K/V global bf16 hi/lo conversion; V transposed. grid (32, NKV, Bq), 256 thr
// ---------------------------------------------------------------------------
__global__ __launch_bounds__(256) void convert_kv()
{
    int jt = blockIdx.x, hk = blockIdx.y, b = blockIdx.z;
    int tid = threadIdx.x;
    __shared__ float vt[64][65];

    int r    = tid >> 2;          // 0..63
    int dseg = (tid & 3) * 16;    // 0,16,32,48

    const float* ksrc = g_qkv + (size_t)(b * Sq + jt * 64 + r) * QKVW + NH * HD + hk * HD;
    const float* vsrc = g_qkv + (size_t)(b * Sq + jt * 64 + r) * QKVW + (NH + NKV) * HD + hk * HD;
    __nv_bfloat16* khid = g_k_hi + ((size_t)(b * NKV + hk) * Sq + jt * 64 + r) * HD;
    __nv_bfloat16* klod = g_k_lo + ((size_t)(b * NKV + hk) * Sq + jt * 64 + r) * HD;

    #pragma unroll
    for (int i = 0; i < 4; i++) {
        int d = dseg + i * 4;
        float4 f = *(const float4*)(ksrc + d);
        uint32_t h01 = packbf(f.x, f.y), h23 = packbf(f.z, f.w);
        float2 u01 = unpackbf(h01), u23 = unpackbf(h23);
        uint32_t l01 = packbf(f.x - u01.x, f.y - u01.y);
        uint32_t l23 = packbf(f.z - u23.x, f.w - u23.y);
        *(uint2*)(khid + d) = make_uint2(h01, h23);
        *(uint2*)(klod + d) = make_uint2(l01, l23);

        float4 v = *(const float4*)(vsrc + d);
        vt[r][d + 0] = v.x; vt[r][d + 1] = v.y; vt[r][d + 2] = v.z; vt[r][d + 3] = v.w;
    }
    __syncthreads();

    int d = tid >> 2;
    int kseg = (tid & 3) * 16;
    uint32_t hi8[8], lo8[8];
    #pragma unroll
    for (int i = 0; i < 8; i++) {
        float a = vt[kseg + 2 * i][d];
        float c = vt[kseg + 2 * i + 1][d];
        uint32_t h = packbf(a, c);
        float2 u = unpackbf(h);
        hi8[i] = h;
        lo8[i] = packbf(a - u.x, c - u.y);
    }
    size_t vo = ((size_t)(b * NKV + hk) * HD + d) * Sq + jt * 64 + kseg;
    *(uint4*)(g_vt_hi + vo)     = make_uint4(hi8[0], hi8[1], hi8[2], hi8[3]);
    *(uint4*)(g_vt_hi + vo + 8) = make_uint4(hi8[4], hi8[5], hi8[6], hi8[7]);
    *(uint4*)(g_vt_lo + vo)     = make_uint4(lo8[0], lo8[1], lo8[2], lo8[3]);
    *(uint4*)(g_vt_lo + vo + 8) = make_uint4(lo8[4], lo8[5], lo8[6], lo8[7]);
}

// ---------------------------------------------------------------------------
// mma.sync flash attention. grid (16, NH, Bq), 256 threads (8 warps x m16).
// q-tile 128, kv-chunk 128 per stage, one __syncthreads per chunk.
// ---------------------------------------------------------------------------
#define ATT_KROWB  144
#define ATT_KTILE  (128 * ATT_KROWB)   /* 18432 */
#define ATT_VROWB  272
#define ATT_VTILE  (64 * ATT_VROWB)    /* 17408 */
#define ATT_VOFF   (2 * ATT_KTILE)     /* 36864 */
#define ATT_STAGEB (ATT_VOFF + 2 * ATT_VTILE)  /* 71680 */
#define ATT_SMEM   (2 * ATT_STAGEB)    /* 143360 */

__global__ __launch_bounds__(256, 1) void attn_mma()
{
    const int qt = (int)gridDim.x - 1 - (int)blockIdx.x;   // big tiles first
    const int h  = blockIdx.y;
    const int b  = blockIdx.z;
    const int hk = h / GROUP;
    const int q0 = qt * 128;

    extern __shared__ char smem[];
    const uint32_t sb = smem_u32(smem);
    const int tid  = threadIdx.x;
    const int wid  = tid >> 5;
    const int lane = tid & 31;
    const int wm   = wid * 16;
    const int g  = lane >> 2;
    const int tg = lane & 3;
    const int q  = lane >> 3;
    const int ri = lane & 7;
    const int b_row_add = ((q >> 1) << 3) + ri;
    const int b_col_add = (q & 1) << 3;

    // ---- Q fragments (scaled, hi/lo split) ----
    uint32_t qa_hi[4][4], qa_lo[4][4];
    {
        const float* qbase = g_qkv + (size_t)(b * Sq + q0 + wm) * QKVW + h * HD;
        #pragma unroll
        for (int kb = 0; kb < 4; kb++) {
            #pragma unroll
            for (int p = 0; p < 4; p++) {
                int row = g + (p & 1) * 8;
                int col = kb * 16 + tg * 2 + (p >> 1) * 8;
                float2 f = *(const float2*)(qbase + (size_t)row * QKVW + col);
                f.x *= QSCALE; f.y *= QSCALE;
                uint32_t hh = packbf(f.x, f.y);
                float2 u = unpackbf(hh);
                qa_hi[kb][p] = hh;
                qa_lo[kb][p] = packbf(f.x - u.x, f.y - u.y);
            }
        }
    }

    float oacc[8][4];
    #pragma unroll
    for (int n = 0; n < 8; n++)
        #pragma unroll
        for (int j = 0; j < 4; j++) oacc[n][j] = 0.f;
    float m0 = -1e30f, m1 = -1e30f, l0 = 0.f, l1 = 0.f;

    const __nv_bfloat16* khi = g_k_hi  + (size_t)(b * NKV + hk) * Sq * HD;
    const __nv_bfloat16* klo = g_k_lo  + (size_t)(b * NKV + hk) * Sq * HD;
    const __nv_bfloat16* vhi = g_vt_hi + (size_t)(b * NKV + hk) * HD * Sq;
    const __nv_bfloat16* vlo = g_vt_lo + (size_t)(b * NKV + hk) * HD * Sq;

    const int nchunks = qt + 1;   // 128-kv chunks

    auto load = [&](int stg, int ct) {
        uint32_t dst = sb + stg * ATT_STAGEB;
        int j0 = ct * 128;
        #pragma unroll
        for (int k = 0; k < 16; k++) {
            int c = tid + k * 256;
            int t = c >> 10;
            if (t < 2) {
                int row = (c >> 3) & 127;
                int seg = c & 7;
                const __nv_bfloat16* src = (t == 0 ? khi : klo) + (size_t)(j0 + row) * HD + seg * 8;
                CP_ASYNC16(dst + t * ATT_KTILE + row * ATT_KROWB + seg * 16, src);
            } else {
                int row = (c >> 4) & 63;
                int seg = c & 15;
                const __nv_bfloat16* src = (t == 2 ? vhi : vlo) + (size_t)row * Sq + j0 + seg * 8;
                CP_ASYNC16(dst + ATT_VOFF + (t - 2) * ATT_VTILE + row * ATT_VROWB + seg * 16, src);
            }
        }
        CP_COMMIT();
    };

    load(0, 0);

    for (int t = 0; t < nchunks; t++) {
        const int s = t & 1;
        cp_wait<0>();
        __syncthreads();
        if (t + 1 < nchunks) load(s ^ 1, t + 1);

        const uint32_t st = sb + s * ATT_STAGEB;
        #pragma unroll
        for (int half = 0; half < 2; half++) {
            const int j0 = t * 128 + half * 64;
            if (j0 <= q0 + wm + 15) {
                // ---- S = Q @ K^T (3-product) ----
                float sc[8][4];
                #pragma unroll
                for (int n = 0; n < 8; n++)
                    #pragma unroll
                    for (int j = 0; j < 4; j++) sc[n][j] = 0.f;

                #pragma unroll
                for (int kb = 0; kb < 4; kb++) {
                    #pragma unroll
                    for (int nj = 0; nj < 4; nj++) {
                        uint32_t bh[4], bl[4];
                        uint32_t addr = st + (half * 64 + nj * 16 + b_row_add) * ATT_KROWB
                                        + (kb * 16 + b_col_add) * 2;
                        LDMATRIX_X4(bh, addr);
                        LDMATRIX_X4(bl, addr + ATT_KTILE);
                        #pragma unroll
                        for (int hh = 0; hh < 2; hh++) {
                            int n = nj * 2 + hh;
                            MMA_BF16(sc[n], qa_hi[kb], bh[hh*2], bh[hh*2+1]);
                            MMA_BF16(sc[n], qa_hi[kb], bl[hh*2], bl[hh*2+1]);
                            MMA_BF16(sc[n], qa_lo[kb], bh[hh*2], bh[hh*2+1]);
                        }
                    }
                }

                // ---- causal mask (diagonal tiles) ----
                if (j0 + 63 > q0 + wm) {
                    int r0 = q0 + wm + g;
                    #pragma unroll
                    for (int n = 0; n < 8; n++) {
                        int cb = j0 + n * 8 + tg * 2;
                        if (cb     > r0)     sc[n][0] = -1e30f;
                        if (cb + 1 > r0)     sc[n][1] = -1e30f;
                        if (cb     > r0 + 8) sc[n][2] = -1e30f;
                        if (cb + 1 > r0 + 8) sc[n][3] = -1e30f;
                    }
                }

                // ---- online softmax ----
                float mx0 = -1e30f, mx1 = -1e30f;
                #pragma unroll
                for (int n = 0; n < 8; n++) {
                    mx0 = fmaxf(mx0, fmaxf(sc[n][0], sc[n][1]));
                    mx1 = fmaxf(mx1, fmaxf(sc[n][2], sc[n][3]));
                }
                mx0 = fmaxf(mx0, __shfl_xor_sync(0xffffffffu, mx0, 1));
                mx0 = fmaxf(mx0, __shfl_xor_sync(0xffffffffu, mx0, 2));
                mx1 = fmaxf(mx1, __shfl_xor_sync(0xffffffffu, mx1, 1));
                mx1 = fmaxf(mx1, __shfl_xor_sync(0xffffffffu, mx1, 2));

                float nm0 = fmaxf(m0, mx0), nm1 = fmaxf(m1, mx1);
                float corr0 = ex2(m0 - nm0), corr1 = ex2(m1 - nm1);
                m0 = nm0; m1 = nm1;

                float s0 = 0.f, s1 = 0.f;
                #pragma unroll
                for (int n = 0; n < 8; n++) {
                    sc[n][0] = ex2(sc[n][0] - nm0);
                    sc[n][1] = ex2(sc[n][1] - nm0);
                    sc[n][2] = ex2(sc[n][2] - nm1);
                    sc[n][3] = ex2(sc[n][3] - nm1);
                    s0 += sc[n][0] + sc[n][1];
                    s1 += sc[n][2] + sc[n][3];
                }
                s0 += __shfl_xor_sync(0xffffffffu, s0, 1);
                s0 += __shfl_xor_sync(0xffffffffu, s0, 2);
                s1 += __shfl_xor_sync(0xffffffffu, s1, 1);
                s1 += __shfl_xor_sync(0xffffffffu, s1, 2);
                l0 = l0 * corr0 + s0;
                l1 = l1 * corr1 + s1;

                #pragma unroll
                for (int n = 0; n < 8; n++) {
                    oacc[n][0] *= corr0; oacc[n][1] *= corr0;
                    oacc[n][2] *= corr1; oacc[n][3] *= corr1;
                }

                // ---- pack P (hi/lo) as a-frags ----
                uint32_t pa_hi[4][4], pa_lo[4][4];
                #pragma unroll
                for (int kb = 0; kb < 4; kb++) {
                    #pragma unroll
                    for (int hh = 0; hh < 2; hh++) {
                        int n = 2 * kb + hh;
                        uint32_t h0 = packbf(sc[n][0], sc[n][1]);
                        uint32_t h1 = packbf(sc[n][2], sc[n][3]);
                        float2 u0 = unpackbf(h0), u1 = unpackbf(h1);
                        pa_hi[kb][hh * 2 + 0] = h0;
                        pa_hi[kb][hh * 2 + 1] = h1;
                        pa_lo[kb][hh * 2 + 0] = packbf(sc[n][0] - u0.x, sc[n][1] - u0.y);
                        pa_lo[kb][hh * 2 + 1] = packbf(sc[n][2] - u1.x, sc[n][3] - u1.y);
                    }
                }

                // ---- O += P @ V (3-product) ----
                #pragma unroll
                for (int kb = 0; kb < 4; kb++) {
                    #pragma unroll
                    for (int dg = 0; dg < 4; dg++) {
                        uint32_t vh[4], vl[4];
                        uint32_t addr = st + ATT_VOFF + (dg * 16 + b_row_add) * ATT_VROWB
                                        + (half * 64 + kb * 16 + b_col_add) * 2;
                        LDMATRIX_X4(vh, addr);
                        LDMATRIX_X4(vl, addr + ATT_VTILE);
                        #pragma unroll
                        for (int hh = 0; hh < 2; hh++) {
                            int n = dg * 2 + hh;
                            MMA_BF16(oacc[n], pa_hi[kb], vh[hh*2], vh[hh*2+1]);
                            MMA_BF16(oacc[n], pa_hi[kb], vl[hh*2], vl[hh*2+1]);
                            MMA_BF16(oacc[n], pa_lo[kb], vh[hh*2], vh[hh*2+1]);
                        }
                    }
                }
            }
        }
    }

    // ---- epilogue ----
    float inv0 = 1.f / l0, inv1 = 1.f / l1;
    int row0 = q0 + wm + g;
    #pragma unroll
    for (int n = 0; n < 8; n++) {
        int col = h * HD + n * 8 + tg * 2;
        size_t o0 = (size_t)(b * Sq + row0) * N_HID + col;
        size_t o1 = (size_t)(b * Sq + row0 + 8) * N_HID + col;
        float a0 = oacc[n][0] * inv0, a1 = oacc[n][1] * inv0;
        float a2 = oacc[n][2] * inv1, a3 = oacc[n][3] * inv1;
        uint32_t h0 = packbf(a0, a1), h1 = packbf(a2, a3);
        float2 u0 = unpackbf(h0), u1 = unpackbf(h1);
        *(uint32_t*)(g_attn_hi + o0) = h0;
        *(uint32_t*)(g_attn_hi + o1) = h1;
        *(uint32_t*)(g_attn_lo + o0) = packbf(a0 - u0.x, a1 - u0.y);
        *(uint32_t*)(g_attn_lo + o1) = packbf(a2 - u1.x, a3 - u1.y);
    }
}

// ---------------------------------------------------------------------------
// Launch pipeline
// ---------------------------------------------------------------------------
extern "C" void kernel_launch(void* const* d_in, const int* in_sizes, int n_in,
                              void* d_out, int out_size)
{
    const int*   positions = (const int*)d_in[0];
    const float* hidden    = (const float*)d_in[1];
    const float* Wqkv      = (const float*)d_in[2];
    const float* Wo        = (const float*)d_in[3];
    float*       out       = (float*)d_out;

    float* qkv;
    cudaGetSymbolAddress((void**)&qkv, g_qkv);
    __nv_bfloat16 *hid_hi, *hid_lo, *wqkvT_hi, *wqkvT_lo, *woT_hi, *woT_lo, *attn_hi, *attn_lo;
    cudaGetSymbolAddress((void**)&hid_hi,   g_hid_hi);
    cudaGetSymbolAddress((void**)&hid_lo,   g_hid_lo);
    cudaGetSymbolAddress((void**)&wqkvT_hi, g_wqkvT_hi);
    cudaGetSymbolAddress((void**)&wqkvT_lo, g_wqkvT_lo);
    cudaGetSymbolAddress((void**)&woT_hi,   g_woT_hi);
    cudaGetSymbolAddress((void**)&woT_lo,   g_woT_lo);
    cudaGetSymbolAddress((void**)&attn_hi,  g_attn_hi);
    cudaGetSymbolAddress((void**)&attn_lo,  g_attn_lo);

    cudaFuncSetAttribute(gemm_mma, cudaFuncAttributeMaxDynamicSharedMemorySize, GEMM_SMEM);
    cudaFuncSetAttribute(attn_mma, cudaFuncAttributeMaxDynamicSharedMemorySize, ATT_SMEM);

    // hidden -> bf16 hi/lo
    {
        int n4 = (MROWS * HIDD) / 4;
        convert_split<<<(n4 + 255) / 256, 256>>>(hidden, hid_hi, hid_lo, n4);
    }
    // Wqkv -> transposed bf16 hi/lo
    transpose_split<<<dim3(QKVW / 32, HIDD / 32), dim3(32, 8)>>>(Wqkv, wqkvT_hi, wqkvT_lo, HIDD, QKVW);

    // QKV projection
    gemm_mma<<<dim3(QKVW / 128, MROWS / 256), 256, GEMM_SMEM>>>(
        MROWS, QKVW, HIDD, hid_hi, hid_lo, wqkvT_hi, wqkvT_lo, qkv);

    // RoPE (q + k)
    {
        int total = Bq * Sq * (NH + NKV) * (HD / 2);
        rope_kernel<<<(total + 255) / 256, 256>>>(positions);
    }

    // K/V -> bf16 hi/lo (V transposed)
    convert_kv<<<dim3(Sq / 64, NKV, Bq), 256>>>();

    // Flash attention (writes g_attn_hi/lo)
    attn_mma<<<dim3(Sq / 128, NH, Bq), 256, ATT_SMEM>>>();

    // Wo -> transposed bf16 hi/lo
    transpose_split<<<dim3(HIDD / 32, N_HID / 32), dim3(32, 8)>>>(Wo, woT_hi, woT_lo, N_HID, HIDD);

    // Output projection
    gemm_mma<<<dim3(HIDD / 128, MROWS / 256), 256, GEMM_SMEM>>>(
        MROWS, HIDD, N_HID, attn_hi, attn_lo, woT_hi, woT_lo, out);
}